// round 8
// baseline (speedup 1.0000x reference)
#include <cuda_runtime.h>

#define CHN 128
#define NMAX 100000
#define EMAX 800000
#define NB 148          // persistent grid = one CTA per SM (all resident)
#define NT 512
#define CHUNK 676       // ceil(NMAX/NB); NB*CHUNK = 100048 >= NMAX

static __device__ float g_deg[NMAX];               // degree -> rsqrt(degree)
static __device__ float g_h[(size_t)NMAX * CHN];   // aggregated features
static __device__ int   g_rowptr[NMAX];
static __device__ int   g_cursor[NMAX];            // cursors -> per-row counts
static __device__ int   g_csrsrc[EMAX];
static __device__ int   g_aux[NB];                 // per-CTA chunk sums
static __device__ unsigned g_cnt[8];               // grid-barrier counters

__device__ __forceinline__ unsigned cvt_tf32(float f) {
    unsigned r;
    asm("cvt.rna.tf32.f32 %0, %1;" : "=r"(r) : "f"(f));
    return r;
}

__global__ void k_reset() {
    if (threadIdx.x < 8) g_cnt[threadIdx.x] = 0u;
}

__device__ __forceinline__ void gridbar(int k) {
    __syncthreads();
    __threadfence();
    if (threadIdx.x == 0) {
        atomicAdd(&g_cnt[k], 1u);
        while (*(volatile unsigned*)&g_cnt[k] < (unsigned)NB) __nanosleep(32);
    }
    __syncthreads();
}

// ---------------------------------------------------------------------------
// Persistent preprocessing + SpMM: phases separated by grid barriers.
// ---------------------------------------------------------------------------
__global__ void __launch_bounds__(NT, 1) k_prep(const float4* __restrict__ x4,
                                                const int* __restrict__ src,
                                                const int* __restrict__ dst,
                                                int n, int e) {
    const int tid = threadIdx.x, cta = blockIdx.x;
    const int gthread = cta * NT + tid;
    const int gstride = NB * NT;

    // ---- Phase A: deg = 1 (self loop) ----
    for (int i = gthread; i < n; i += gstride) g_deg[i] = 1.0f;
    gridbar(0);

    // ---- Phase B: degree histogram ----
    for (int i = gthread; i < e; i += gstride) atomicAdd(&g_deg[dst[i]], 1.0f);
    gridbar(1);

    // ---- Phase C: per-chunk scan of (deg-1); 2 elements per thread ----
    __shared__ int ws[16];
    __shared__ int smaux[NB];
    int i0 = cta * CHUNK + 2 * tid;
    float dg0 = 1.f, dg1 = 1.f;
    int v0 = 0, v1 = 0;
    bool e0 = (2 * tid < CHUNK) && (i0 < n);
    bool e1 = (2 * tid + 1 < CHUNK) && (i0 + 1 < n);
    if (e0) { dg0 = g_deg[i0];     v0 = (int)dg0 - 1; }
    if (e1) { dg1 = g_deg[i0 + 1]; v1 = (int)dg1 - 1; }
    int v = v0 + v1;
    int x = v;
#pragma unroll
    for (int o = 1; o < 32; o <<= 1) {
        int y = __shfl_up_sync(~0u, x, o);
        if ((tid & 31) >= o) x += y;
    }
    if ((tid & 31) == 31) ws[tid >> 5] = x;
    __syncthreads();
    if (tid < 16) {
        int s = ws[tid];
#pragma unroll
        for (int o = 1; o < 16; o <<= 1) {
            int y = __shfl_up_sync(0xFFFF, s, o);
            if (tid >= o) s += y;
        }
        ws[tid] = s;   // inclusive warp sums
    }
    __syncthreads();
    int wbase = (tid >= 32) ? ws[(tid >> 5) - 1] : 0;
    int ex = wbase + x - v;          // block-exclusive prefix for this thread
    if (tid == 0) g_aux[cta] = ws[15];   // chunk total
    gridbar(2);

    // scan chunk totals (each CTA redundantly; serial 148 adds on thread 0)
    if (tid < NB) smaux[tid] = g_aux[tid];
    __syncthreads();
    if (tid == 0) {
        int run = 0;
        for (int j = 0; j < NB; j++) { int t = smaux[j]; smaux[j] = run; run += t; }
    }
    __syncthreads();
    int rbase = smaux[cta];
    if (e0) { g_rowptr[i0] = rbase + ex;          g_deg[i0] = rsqrtf(dg0);     g_cursor[i0] = 0; }
    if (e1) { g_rowptr[i0 + 1] = rbase + ex + v0; g_deg[i0 + 1] = rsqrtf(dg1); g_cursor[i0 + 1] = 0; }
    gridbar(3);

    // ---- Phase D: scatter edges into CSR ----
    for (int i = gthread; i < e; i += gstride) {
        int d = dst[i];
        int pos = g_rowptr[d] + atomicAdd(&g_cursor[d], 1);
        g_csrsrc[pos] = src[i];
    }
    gridbar(4);

    // ---- Phase E: CSR SpMM, one warp per row (grid-stride) ----
    const int lane = tid & 31;
    const int gw = gthread >> 5;
    const int nwarps = gstride >> 5;
    for (int w = gw; w < n; w += nwarps) {
        float dd = g_deg[w];
        float4 acc = x4[(size_t)w * 32 + lane];
        float c = dd * dd;
        acc.x *= c; acc.y *= c; acc.z *= c; acc.w *= c;
        int beg = g_rowptr[w];
        int cnt = g_cursor[w];
        for (int c0 = 0; c0 < cnt; c0 += 32) {
            int m = min(32, cnt - c0);
            int s = 0;
            float wv = 0.f;
            if (lane < m) {
                s = g_csrsrc[beg + c0 + lane];
                wv = g_deg[s] * dd;
            }
            int j = 0;
            for (; j + 8 <= m; j += 8) {
                int si[8]; float ni[8]; float4 vv[8];
#pragma unroll
                for (int q = 0; q < 8; q++) {
                    si[q] = __shfl_sync(~0u, s, j + q);
                    ni[q] = __shfl_sync(~0u, wv, j + q);
                }
#pragma unroll
                for (int q = 0; q < 8; q++) vv[q] = x4[(size_t)si[q] * 32 + lane];
#pragma unroll
                for (int q = 0; q < 8; q++) {
                    acc.x += ni[q] * vv[q].x; acc.y += ni[q] * vv[q].y;
                    acc.z += ni[q] * vv[q].z; acc.w += ni[q] * vv[q].w;
                }
            }
            for (; j + 4 <= m; j += 4) {
                int si[4]; float ni[4]; float4 vv[4];
#pragma unroll
                for (int q = 0; q < 4; q++) {
                    si[q] = __shfl_sync(~0u, s, j + q);
                    ni[q] = __shfl_sync(~0u, wv, j + q);
                }
#pragma unroll
                for (int q = 0; q < 4; q++) vv[q] = x4[(size_t)si[q] * 32 + lane];
#pragma unroll
                for (int q = 0; q < 4; q++) {
                    acc.x += ni[q] * vv[q].x; acc.y += ni[q] * vv[q].y;
                    acc.z += ni[q] * vv[q].z; acc.w += ni[q] * vv[q].w;
                }
            }
            for (; j < m; j++) {
                int sj = __shfl_sync(~0u, s, j);
                float nr = __shfl_sync(~0u, wv, j);
                float4 vv = x4[(size_t)sj * 32 + lane];
                acc.x += nr * vv.x; acc.y += nr * vv.y;
                acc.z += nr * vv.z; acc.w += nr * vv.w;
            }
        }
        reinterpret_cast<float4*>(g_h)[(size_t)w * 32 + lane] = acc;
    }
}

// ---------------------------------------------------------------------------
// GEMM: out = relu([h|x0] @ (beta*[W1;W2] + c1*[I;I]))   via tf32 mma.sync
// Double-buffered smem stages, one sync per K-chunk (unchanged from R7).
// ---------------------------------------------------------------------------
#define SA 36
#define SB 136
#define STAGE_WORDS (128 * SA + 32 * SB)     // 8960 words = 35840 B

__global__ void __launch_bounds__(256, 2) k_gemm(const float* __restrict__ x0,
                                                 const float* __restrict__ w1,
                                                 const float* __restrict__ w2,
                                                 float* __restrict__ out, int n) {
    extern __shared__ unsigned dynsm[];
    const float BETA = 0.6931471805599453f;
    const float C1 = 0.15342640972002733f;

    int tid = threadIdx.x, warp = tid >> 5, lane = tid & 31;
    int g = lane >> 2, t4 = lane & 3;
    int row0 = blockIdx.x * 128;

    float4 ra[4];
    float4 rw[4];

    auto loadA = [&](int kc) {
        const float* Asrc = (kc < 4) ? g_h : x0;
        int kbase = (kc & 3) * 32;
#pragma unroll
        for (int i = 0; i < 4; i++) {
            int t = tid + i * 256;
            int r = t >> 3, q = t & 7;
            int gr = row0 + r;
            ra[i] = (gr < n) ? *(const float4*)(Asrc + (size_t)gr * CHN + kbase + q * 4)
                             : make_float4(0.f, 0.f, 0.f, 0.f);
        }
    };
    auto loadW = [&](int kc) {
#pragma unroll
        for (int i = 0; i < 4; i++) {
            int t = tid + i * 256;
            int kk = t >> 5, q = t & 31;
            int kg = kc * 32 + kk;
            const float* Wr = (kg < 128) ? (w1 + (size_t)kg * CHN)
                                         : (w2 + (size_t)(kg - 128) * CHN);
            rw[i] = *(const float4*)(Wr + q * 4);
        }
    };
    auto storeStage = [&](int kc, unsigned* As, unsigned* Ws) {
#pragma unroll
        for (int i = 0; i < 4; i++) {
            int t = tid + i * 256;
            int r = t >> 3, q = t & 7;
            uint4 u = make_uint4(cvt_tf32(ra[i].x), cvt_tf32(ra[i].y),
                                 cvt_tf32(ra[i].z), cvt_tf32(ra[i].w));
            *reinterpret_cast<uint4*>(&As[r * SA + q * 4]) = u;
        }
#pragma unroll
        for (int i = 0; i < 4; i++) {
            int t = tid + i * 256;
            int kk = t >> 5, q = t & 31;
            int kg = kc * 32 + kk, kd = kg & 127, c = q * 4;
            uint4 u;
            u.x = cvt_tf32(BETA * rw[i].x + (kd == c + 0 ? C1 : 0.f));
            u.y = cvt_tf32(BETA * rw[i].y + (kd == c + 1 ? C1 : 0.f));
            u.z = cvt_tf32(BETA * rw[i].z + (kd == c + 2 ? C1 : 0.f));
            u.w = cvt_tf32(BETA * rw[i].w + (kd == c + 3 ? C1 : 0.f));
            *reinterpret_cast<uint4*>(&Ws[kk * SB + c]) = u;
        }
    };

    float acc[16][4];
#pragma unroll
    for (int nt = 0; nt < 16; nt++)
#pragma unroll
        for (int j = 0; j < 4; j++) acc[nt][j] = 0.f;

    loadA(0);
    loadW(0);
    storeStage(0, dynsm, dynsm + 128 * SA);
    __syncthreads();

    for (int kc = 0; kc < 8; kc++) {
        unsigned* Ac = dynsm + (kc & 1) * STAGE_WORDS;
        unsigned* Wc = Ac + 128 * SA;
        if (kc < 7) { loadA(kc + 1); loadW(kc + 1); }

#pragma unroll
        for (int k8 = 0; k8 < 4; k8++) {
            int ar = warp * 16 + g;
            int kb = k8 * 8;
            unsigned a0 = Ac[ar * SA + kb + t4];
            unsigned a1 = Ac[(ar + 8) * SA + kb + t4];
            unsigned a2 = Ac[ar * SA + kb + t4 + 4];
            unsigned a3 = Ac[(ar + 8) * SA + kb + t4 + 4];
#pragma unroll
            for (int nt = 0; nt < 16; nt++) {
                unsigned b0 = Wc[(kb + t4) * SB + nt * 8 + g];
                unsigned b1 = Wc[(kb + t4 + 4) * SB + nt * 8 + g];
                asm volatile(
                    "mma.sync.aligned.m16n8k8.row.col.f32.tf32.tf32.f32 "
                    "{%0,%1,%2,%3}, {%4,%5,%6,%7}, {%8,%9}, {%0,%1,%2,%3};"
                    : "+f"(acc[nt][0]), "+f"(acc[nt][1]),
                      "+f"(acc[nt][2]), "+f"(acc[nt][3])
                    : "r"(a0), "r"(a1), "r"(a2), "r"(a3), "r"(b0), "r"(b1));
            }
        }

        if (kc < 7) {
            unsigned* An = dynsm + ((kc + 1) & 1) * STAGE_WORDS;
            storeStage(kc + 1, An, An + 128 * SA);
            __syncthreads();
        }
    }

    int r1 = row0 + warp * 16 + g;
    int r2 = r1 + 8;
#pragma unroll
    for (int nt = 0; nt < 16; nt++) {
        int c = nt * 8 + t4 * 2;
        if (r1 < n) {
            float2 o = make_float2(fmaxf(acc[nt][0], 0.f), fmaxf(acc[nt][1], 0.f));
            *reinterpret_cast<float2*>(out + (size_t)r1 * CHN + c) = o;
        }
        if (r2 < n) {
            float2 o = make_float2(fmaxf(acc[nt][2], 0.f), fmaxf(acc[nt][3], 0.f));
            *reinterpret_cast<float2*>(out + (size_t)r2 * CHN + c) = o;
        }
    }
}

// ---------------------------------------------------------------------------
extern "C" void kernel_launch(void* const* d_in, const int* in_sizes, int n_in,
                              void* d_out, int out_size) {
    const float* x  = (const float*)d_in[0];
    const float* x0 = (const float*)d_in[1];
    const float* w1 = (const float*)d_in[2];
    const float* w2 = (const float*)d_in[3];
    const int*   ei = (const int*)d_in[4];
    float* out = (float*)d_out;

    const int n = in_sizes[0] / CHN;   // 100000
    const int e = in_sizes[4] / 2;     // 800000
    const int* src = ei;
    const int* dst = ei + e;
    const int gemm_smem = 2 * STAGE_WORDS * 4;   // 71680 B

    cudaFuncSetAttribute(k_gemm, cudaFuncAttributeMaxDynamicSharedMemorySize,
                         gemm_smem);   // host-side config only

    k_reset<<<1, 32>>>();
    k_prep<<<NB, NT>>>((const float4*)x, src, dst, n, e);
    k_gemm<<<(n + 127) / 128, 256, gemm_smem>>>(x0, w1, w2, out, n);
}

// round 9
// speedup vs baseline: 1.1428x; 1.1428x over previous
#include <cuda_runtime.h>

#define CHN 128
#define NMAX 100000
#define EMAX 800000

static __device__ float g_deg[NMAX];               // rsqrt(degree)
static __device__ int   g_cnt[NMAX];               // edge counts per dst (no self loop)
static __device__ float g_h[(size_t)NMAX * CHN];   // aggregated features
static __device__ int   g_rowptr[NMAX];            // CSR row starts
static __device__ int   g_seq[EMAX];               // per-edge slot within its row
static __device__ int   g_csrsrc[EMAX];            // CSR column (src) indices
static __device__ int   g_aux[128];                // scan block sums

__device__ __forceinline__ unsigned cvt_tf32(float f) {
    unsigned r;
    asm("cvt.rna.tf32.f32 %0, %1;" : "=r"(r) : "f"(f));
    return r;
}

// ---------------------------------------------------------------------------
// Stage 1: zero counts
// ---------------------------------------------------------------------------
__global__ void k_init(int n) {
    int i = blockIdx.x * blockDim.x + threadIdx.x;
    if (i < n) g_cnt[i] = 0;
}

// Stage 2: histogram; atomic return value IS the scatter slot.
__global__ void k_hist(const int* __restrict__ dst, int e) {
    int i = blockIdx.x * blockDim.x + threadIdx.x;
    if (i < e) g_seq[i] = atomicAdd(&g_cnt[dst[i]], 1);
}

// ---------------------------------------------------------------------------
// Stage 3: exclusive scan of counts -> rowptr; fused dis = rsqrt(cnt+1)
// ---------------------------------------------------------------------------
__global__ void __launch_bounds__(1024) k_scan1(int n) {
    __shared__ int wsum[32];
    int i = blockIdx.x * 1024 + threadIdx.x;
    int v = (i < n) ? g_cnt[i] : 0;
    if (i < n) g_deg[i] = rsqrtf((float)(v + 1));   // +1 self loop
    int x = v;
#pragma unroll
    for (int o = 1; o < 32; o <<= 1) {
        int y = __shfl_up_sync(~0u, x, o);
        if ((threadIdx.x & 31) >= o) x += y;
    }
    if ((threadIdx.x & 31) == 31) wsum[threadIdx.x >> 5] = x;
    __syncthreads();
    if (threadIdx.x < 32) {
        int s = wsum[threadIdx.x];
#pragma unroll
        for (int o = 1; o < 32; o <<= 1) {
            int y = __shfl_up_sync(~0u, s, o);
            if (threadIdx.x >= o) s += y;
        }
        wsum[threadIdx.x] = s;
    }
    __syncthreads();
    int base = (threadIdx.x >= 32) ? wsum[(threadIdx.x >> 5) - 1] : 0;
    if (i < n) g_rowptr[i] = base + x - v;
    if (threadIdx.x == 1023) g_aux[blockIdx.x] = base + x;
}

__global__ void k_scan2(int nb) {   // nb <= 128
    int tid = threadIdx.x;
    int v = (tid < nb) ? g_aux[tid] : 0;
    int x = v;
#pragma unroll
    for (int o = 1; o < 32; o <<= 1) {
        int y = __shfl_up_sync(~0u, x, o);
        if ((tid & 31) >= o) x += y;
    }
    __shared__ int ws[4];
    if ((tid & 31) == 31) ws[tid >> 5] = x;
    __syncthreads();
    if (tid < 4) {
        int s = ws[tid];
        int r0 = __shfl_up_sync(0xF, s, 1); if (tid >= 1) s += r0;
        int r1 = __shfl_up_sync(0xF, s, 2); if (tid >= 2) s += r1;
        ws[tid] = s;
    }
    __syncthreads();
    int base = (tid >= 32) ? ws[(tid >> 5) - 1] : 0;
    if (tid < nb) g_aux[tid] = base + x - v;   // exclusive
}

__global__ void k_scan3(int n) {
    int i = blockIdx.x * blockDim.x + threadIdx.x;
    if (i < n) g_rowptr[i] += g_aux[i >> 10];
}

// ---------------------------------------------------------------------------
// Stage 4: atomic-free scatter (slot was captured during histogram)
// ---------------------------------------------------------------------------
__global__ void k_scatter(const int* __restrict__ src, const int* __restrict__ dst, int e) {
    int i = blockIdx.x * blockDim.x + threadIdx.x;
    if (i >= e) return;
    int d = dst[i];
    g_csrsrc[g_rowptr[d] + g_seq[i]] = src[i];
}

// ---------------------------------------------------------------------------
// Stage 5: CSR SpMM — one warp per dst row; gather batches of 8/4/1.
// ---------------------------------------------------------------------------
__global__ void __launch_bounds__(256) k_spmm(const float4* __restrict__ x4, int n) {
    int w = (blockIdx.x * 256 + threadIdx.x) >> 5;
    int lane = threadIdx.x & 31;
    if (w >= n) return;
    float dd = g_deg[w];
    float4 acc = x4[(size_t)w * 32 + lane];
    float c = dd * dd;
    acc.x *= c; acc.y *= c; acc.z *= c; acc.w *= c;
    int beg = g_rowptr[w];
    int cnt = g_cnt[w];
    for (int c0 = 0; c0 < cnt; c0 += 32) {
        int m = min(32, cnt - c0);
        int s = 0;
        float wv = 0.f;
        if (lane < m) {
            s = g_csrsrc[beg + c0 + lane];
            wv = g_deg[s] * dd;
        }
        int j = 0;
        for (; j + 8 <= m; j += 8) {
            int si[8]; float ni[8]; float4 v[8];
#pragma unroll
            for (int q = 0; q < 8; q++) {
                si[q] = __shfl_sync(~0u, s, j + q);
                ni[q] = __shfl_sync(~0u, wv, j + q);
            }
#pragma unroll
            for (int q = 0; q < 8; q++) v[q] = x4[(size_t)si[q] * 32 + lane];
#pragma unroll
            for (int q = 0; q < 8; q++) {
                acc.x += ni[q] * v[q].x; acc.y += ni[q] * v[q].y;
                acc.z += ni[q] * v[q].z; acc.w += ni[q] * v[q].w;
            }
        }
        for (; j + 4 <= m; j += 4) {
            int si[4]; float ni[4]; float4 v[4];
#pragma unroll
            for (int q = 0; q < 4; q++) {
                si[q] = __shfl_sync(~0u, s, j + q);
                ni[q] = __shfl_sync(~0u, wv, j + q);
            }
#pragma unroll
            for (int q = 0; q < 4; q++) v[q] = x4[(size_t)si[q] * 32 + lane];
#pragma unroll
            for (int q = 0; q < 4; q++) {
                acc.x += ni[q] * v[q].x; acc.y += ni[q] * v[q].y;
                acc.z += ni[q] * v[q].z; acc.w += ni[q] * v[q].w;
            }
        }
        for (; j < m; j++) {
            int sj = __shfl_sync(~0u, s, j);
            float nr = __shfl_sync(~0u, wv, j);
            float4 v = x4[(size_t)sj * 32 + lane];
            acc.x += nr * v.x; acc.y += nr * v.y;
            acc.z += nr * v.z; acc.w += nr * v.w;
        }
    }
    reinterpret_cast<float4*>(g_h)[(size_t)w * 32 + lane] = acc;
}

// ---------------------------------------------------------------------------
// Stage 6: out = relu([h|x0] @ (beta*[W1;W2] + c1*[I;I]))  via tf32 mma.sync
// Double-buffered smem stages, one sync per K-chunk.
// ---------------------------------------------------------------------------
#define SA 36
#define SB 136
#define STAGE_WORDS (128 * SA + 32 * SB)     // 8960 words = 35840 B

__global__ void __launch_bounds__(256, 2) k_gemm(const float* __restrict__ x0,
                                                 const float* __restrict__ w1,
                                                 const float* __restrict__ w2,
                                                 float* __restrict__ out, int n) {
    extern __shared__ unsigned dynsm[];
    const float BETA = 0.6931471805599453f;
    const float C1 = 0.15342640972002733f;

    int tid = threadIdx.x, warp = tid >> 5, lane = tid & 31;
    int g = lane >> 2, t4 = lane & 3;
    int row0 = blockIdx.x * 128;

    float4 ra[4];
    float4 rw[4];

    auto loadA = [&](int kc) {
        const float* Asrc = (kc < 4) ? g_h : x0;
        int kbase = (kc & 3) * 32;
#pragma unroll
        for (int i = 0; i < 4; i++) {
            int t = tid + i * 256;
            int r = t >> 3, q = t & 7;
            int gr = row0 + r;
            ra[i] = (gr < n) ? *(const float4*)(Asrc + (size_t)gr * CHN + kbase + q * 4)
                             : make_float4(0.f, 0.f, 0.f, 0.f);
        }
    };
    auto loadW = [&](int kc) {
#pragma unroll
        for (int i = 0; i < 4; i++) {
            int t = tid + i * 256;
            int kk = t >> 5, q = t & 31;
            int kg = kc * 32 + kk;
            const float* Wr = (kg < 128) ? (w1 + (size_t)kg * CHN)
                                         : (w2 + (size_t)(kg - 128) * CHN);
            rw[i] = *(const float4*)(Wr + q * 4);
        }
    };
    auto storeStage = [&](int kc, unsigned* As, unsigned* Ws) {
#pragma unroll
        for (int i = 0; i < 4; i++) {
            int t = tid + i * 256;
            int r = t >> 3, q = t & 7;
            uint4 u = make_uint4(cvt_tf32(ra[i].x), cvt_tf32(ra[i].y),
                                 cvt_tf32(ra[i].z), cvt_tf32(ra[i].w));
            *reinterpret_cast<uint4*>(&As[r * SA + q * 4]) = u;
        }
#pragma unroll
        for (int i = 0; i < 4; i++) {
            int t = tid + i * 256;
            int kk = t >> 5, q = t & 31;
            int kg = kc * 32 + kk, kd = kg & 127, c = q * 4;
            uint4 u;
            u.x = cvt_tf32(BETA * rw[i].x + (kd == c + 0 ? C1 : 0.f));
            u.y = cvt_tf32(BETA * rw[i].y + (kd == c + 1 ? C1 : 0.f));
            u.z = cvt_tf32(BETA * rw[i].z + (kd == c + 2 ? C1 : 0.f));
            u.w = cvt_tf32(BETA * rw[i].w + (kd == c + 3 ? C1 : 0.f));
            *reinterpret_cast<uint4*>(&Ws[kk * SB + c]) = u;
        }
    };

    float acc[16][4];
#pragma unroll
    for (int nt = 0; nt < 16; nt++)
#pragma unroll
        for (int j = 0; j < 4; j++) acc[nt][j] = 0.f;

    loadA(0);
    loadW(0);
    storeStage(0, dynsm, dynsm + 128 * SA);
    __syncthreads();

    for (int kc = 0; kc < 8; kc++) {
        unsigned* Ac = dynsm + (kc & 1) * STAGE_WORDS;
        unsigned* Wc = Ac + 128 * SA;
        if (kc < 7) { loadA(kc + 1); loadW(kc + 1); }

#pragma unroll
        for (int k8 = 0; k8 < 4; k8++) {
            int ar = warp * 16 + g;
            int kb = k8 * 8;
            unsigned a0 = Ac[ar * SA + kb + t4];
            unsigned a1 = Ac[(ar + 8) * SA + kb + t4];
            unsigned a2 = Ac[ar * SA + kb + t4 + 4];
            unsigned a3 = Ac[(ar + 8) * SA + kb + t4 + 4];
#pragma unroll
            for (int nt = 0; nt < 16; nt++) {
                unsigned b0 = Wc[(kb + t4) * SB + nt * 8 + g];
                unsigned b1 = Wc[(kb + t4 + 4) * SB + nt * 8 + g];
                asm volatile(
                    "mma.sync.aligned.m16n8k8.row.col.f32.tf32.tf32.f32 "
                    "{%0,%1,%2,%3}, {%4,%5,%6,%7}, {%8,%9}, {%0,%1,%2,%3};"
                    : "+f"(acc[nt][0]), "+f"(acc[nt][1]),
                      "+f"(acc[nt][2]), "+f"(acc[nt][3])
                    : "r"(a0), "r"(a1), "r"(a2), "r"(a3), "r"(b0), "r"(b1));
            }
        }

        if (kc < 7) {
            unsigned* An = dynsm + ((kc + 1) & 1) * STAGE_WORDS;
            storeStage(kc + 1, An, An + 128 * SA);
            __syncthreads();
        }
    }

    int r1 = row0 + warp * 16 + g;
    int r2 = r1 + 8;
#pragma unroll
    for (int nt = 0; nt < 16; nt++) {
        int c = nt * 8 + t4 * 2;
        if (r1 < n) {
            float2 o = make_float2(fmaxf(acc[nt][0], 0.f), fmaxf(acc[nt][1], 0.f));
            *reinterpret_cast<float2*>(out + (size_t)r1 * CHN + c) = o;
        }
        if (r2 < n) {
            float2 o = make_float2(fmaxf(acc[nt][2], 0.f), fmaxf(acc[nt][3], 0.f));
            *reinterpret_cast<float2*>(out + (size_t)r2 * CHN + c) = o;
        }
    }
}

// ---------------------------------------------------------------------------
extern "C" void kernel_launch(void* const* d_in, const int* in_sizes, int n_in,
                              void* d_out, int out_size) {
    const float* x  = (const float*)d_in[0];
    const float* x0 = (const float*)d_in[1];
    const float* w1 = (const float*)d_in[2];
    const float* w2 = (const float*)d_in[3];
    const int*   ei = (const int*)d_in[4];
    float* out = (float*)d_out;

    const int n = in_sizes[0] / CHN;   // 100000
    const int e = in_sizes[4] / 2;     // 800000
    const int* src = ei;
    const int* dst = ei + e;
    const int nb = (n + 1023) / 1024;
    const int gemm_smem = 2 * STAGE_WORDS * 4;   // 71680 B

    cudaFuncSetAttribute(k_gemm, cudaFuncAttributeMaxDynamicSharedMemorySize,
                         gemm_smem);   // host-side config only

    k_init<<<(n + 255) / 256, 256>>>(n);
    k_hist<<<(e + 255) / 256, 256>>>(dst, e);
    k_scan1<<<nb, 1024>>>(n);
    k_scan2<<<1, 128>>>(nb);
    k_scan3<<<(n + 255) / 256, 256>>>(n);
    k_scatter<<<(e + 255) / 256, 256>>>(src, dst, e);
    k_spmm<<<(n + 7) / 8, 256>>>((const float4*)x, n);
    k_gemm<<<(n + 127) / 128, 256, gemm_smem>>>(x0, w1, w2, out, n);
}